// round 16
// baseline (speedup 1.0000x reference)
#include <cuda_runtime.h>
#include <cuda_fp16.h>
#include <math.h>
#include <stdint.h>

#define NB 64
#define NR 36
#define NW 50
#define ND 1024
#define MM (NB*NR)    // 2304
#define NN (NB*NW)    // 3200
#define EPSF 1e-8f
#define KSPLIT 4

// ---------------- scratch (device globals) ----------------
__device__ float g_S[MM * NN];                 // unnormalized dot products, 29.5 MB
__device__ float g_Gp[KSPLIT * NB * NW * NW];  // partial Gram matrices
__device__ float g_G[NB * NW * NW];            // reduced Gram matrices
__device__ float g_img_inv[MM];
__device__ __half g_A2[MM * ND];               // 4.7 MB (fp16)
__device__ __half g_B2[NN * ND];               // 6.6 MB (fp16, written by gram_kernel)

// ---------------- small PTX helpers (sm_80-era, compute_103-safe) ----------------
__device__ __forceinline__ uint32_t smem_u32(const void* p) {
    uint32_t a;
    asm("{ .reg .u64 t; cvta.to.shared.u64 t, %1; cvt.u32.u64 %0, t; }" : "=r"(a) : "l"(p));
    return a;
}
__device__ __forceinline__ void cp_async16(uint32_t dst, const void* src) {
    asm volatile("cp.async.cg.shared.global [%0], [%1], 16;" :: "r"(dst), "l"(src) : "memory");
}
#define CP_COMMIT() asm volatile("cp.async.commit_group;" ::: "memory")
#define CP_WAIT2()  asm volatile("cp.async.wait_group 2;" ::: "memory")

__device__ __forceinline__ void ldmx4(uint32_t* r, uint32_t addr) {
    asm volatile("ldmatrix.sync.aligned.m8n8.x4.shared.b16 {%0,%1,%2,%3}, [%4];"
                 : "=r"(r[0]), "=r"(r[1]), "=r"(r[2]), "=r"(r[3]) : "r"(addr));
}
__device__ __forceinline__ void mma_fp16(float* d, const uint32_t* a, const uint32_t* b) {
    asm volatile(
        "mma.sync.aligned.m16n8k16.row.col.f32.f16.f16.f32 "
        "{%0,%1,%2,%3}, {%4,%5,%6,%7}, {%8,%9}, {%0,%1,%2,%3};"
        : "+f"(d[0]), "+f"(d[1]), "+f"(d[2]), "+f"(d[3])
        : "r"(a[0]), "r"(a[1]), "r"(a[2]), "r"(a[3]), "r"(b[0]), "r"(b[1]));
}

// ---------------- Kernel 1: inverse (norm + eps) for every IMAGE row ----------------
// (caption norms come for free from the Gram diagonal in attn)
__global__ void norms_kernel(const float* __restrict__ imgs) {
    int warp = (blockIdx.x * blockDim.x + threadIdx.x) >> 5;
    int lane = threadIdx.x & 31;
    if (warp >= MM) return;
    const float* p = imgs + (size_t)warp * ND;
    float s = 0.f;
#pragma unroll
    for (int k = 0; k < ND / 128; k++) {
        float4 v = *(const float4*)(p + (size_t)(k * 32 + lane) * 4);
        s += v.x * v.x + v.y * v.y + v.z * v.z + v.w * v.w;
    }
#pragma unroll
    for (int off = 16; off; off >>= 1) s += __shfl_xor_sync(0xffffffffu, s, off);
    if (lane == 0) g_img_inv[warp] = 1.0f / (sqrtf(s) + EPSF);
}

// ---------------- Kernel 1b: fp32 -> fp16 conversion of IMAGES only (grid-stride) ------
__global__ void convert_kernel(const float* __restrict__ imgs) {
    const int tot = MM * ND / 4;
    for (int i = blockIdx.x * blockDim.x + threadIdx.x; i < tot; i += gridDim.x * blockDim.x) {
        float4 v = ((const float4*)imgs)[i];
        __half hx = __float2half_rn(v.x), hy = __float2half_rn(v.y),
               hz = __float2half_rn(v.z), hw = __float2half_rn(v.w);
        __half2 h01; h01.x = hx; h01.y = hy;
        __half2 h23; h23.x = hz; h23.y = hw;
        uint2 hp;
        hp.x = *(uint32_t*)&h01; hp.y = *(uint32_t*)&h23;
        *(uint2*)(g_A2 + (size_t)i * 4) = hp;
    }
}

// ---------------- Kernel 2: Gram matrices (k-split x4) + fp16 caps conversion ----------
// While the caps float4 is in registers for the smem tile fill, also emit its
// fp16 conversion to g_B2 (each element is loaded exactly once across the grid).
#define GK 128
__global__ void gram_kernel(const float* __restrict__ caps) {
    __shared__ float tile[NW][GK + 4];
    int c = blockIdx.x;
    int ks = blockIdx.y;
    const float* cp = caps + (size_t)c * NW * ND;
    int tid = threadIdx.x;               // 256 threads
    int tx = tid % 16, ty = tid / 16;
    float acc[4][4] = {};
    int k0 = ks * (ND / KSPLIT);
    for (int kt = k0; kt < k0 + ND / KSPLIT; kt += GK) {
        __syncthreads();
        for (int idx = tid; idx < NW * GK / 4; idx += 256) {
            int f = idx * 4;
            int w = f / GK, k = f % GK;
            float4 v = *(const float4*)(cp + (size_t)w * ND + kt + k);
            tile[w][k] = v.x; tile[w][k + 1] = v.y; tile[w][k + 2] = v.z; tile[w][k + 3] = v.w;
            // fused fp16 conversion of caps (coalesced 8B stores)
            __half2 h01; h01.x = __float2half_rn(v.x); h01.y = __float2half_rn(v.y);
            __half2 h23; h23.x = __float2half_rn(v.z); h23.y = __float2half_rn(v.w);
            uint2 hp;
            hp.x = *(uint32_t*)&h01; hp.y = *(uint32_t*)&h23;
            *(uint2*)(g_B2 + (size_t)(c * NW + w) * ND + kt + k) = hp;
        }
        __syncthreads();
#pragma unroll 4
        for (int k = 0; k < GK; k++) {
            float a[4], b[4];
#pragma unroll
            for (int u = 0; u < 4; u++) { int w = ty + 16 * u; a[u] = (w < NW) ? tile[w][k] : 0.f; }
#pragma unroll
            for (int v2 = 0; v2 < 4; v2++) { int w = tx + 16 * v2; b[v2] = (w < NW) ? tile[w][k] : 0.f; }
#pragma unroll
            for (int u = 0; u < 4; u++)
#pragma unroll
                for (int v2 = 0; v2 < 4; v2++) acc[u][v2] += a[u] * b[v2];
        }
    }
    float* Gp = g_Gp + ((size_t)ks * NB + c) * NW * NW;
#pragma unroll
    for (int u = 0; u < 4; u++)
#pragma unroll
        for (int v2 = 0; v2 < 4; v2++) {
            int w = ty + 16 * u, w2 = tx + 16 * v2;
            if (w < NW && w2 < NW) Gp[w * NW + w2] = acc[u][v2];
        }
}

// ---------------- Kernel 3: fp16 mma.sync GEMM 128x128, K=1024, 4-stage cp.async ----
// (R13-proven: 57.9us. Prologue folds the Gram partial reduction.)
#define BM 128
#define BN 128
#define BK 16
#define NKSTEP (ND / BK)           // 64
#define PITCH 48                   // 32B data + 16B pad per row (conflict-free ldmatrix)
#define ATILE_B (BM * PITCH)       // 6144
#define STAGE_B (2 * ATILE_B)      // 12288
#define NSTAGE 4
#define GTOT (NB * NW * NW)        // 160000 floats = 40000 float4

__global__ void __launch_bounds__(256, 2)
gemm_kernel() {
    __shared__ __align__(128) char smem[NSTAGE * STAGE_B];   // 48 KB
    const int tid = threadIdx.x;
    const int lane = tid & 31;
    const int wid = tid >> 5;
    const int wm = wid & 1;        // 2 warp-rows  -> 64 rows each
    const int wn = wid >> 1;       // 4 warp-cols  -> 32 cols each
    const int bm0 = blockIdx.y * BM;
    const int bn0 = blockIdx.x * BN;

    const uint32_t sbase = smem_u32(smem);

    const int crow = tid >> 1;           // 0..127
    const int cch  = tid & 1;            // 0..1
    const uint32_t cp_off = (uint32_t)crow * PITCH + (uint32_t)cch * 16;
    const __half* a_src = g_A2 + (size_t)(bm0 + crow) * ND + cch * 8;
    const __half* b_src = g_B2 + (size_t)(bn0 + crow) * ND + cch * 8;

    const uint32_t a_ld = (uint32_t)(wm * 64 + (lane & 15)) * PITCH + (uint32_t)(lane >> 4) * 16;
    const uint32_t b_ld = (uint32_t)(wn * 32 + (lane & 15)) * PITCH + (uint32_t)(lane >> 4) * 16;

#pragma unroll
    for (int s = 0; s < 3; s++) {
        uint32_t d = sbase + s * STAGE_B;
        cp_async16(d + cp_off, a_src + s * BK);
        cp_async16(d + ATILE_B + cp_off, b_src + s * BK);
        CP_COMMIT();
    }

    // ---- folded Gram reduction (overlaps the async prologue) ----
    {
        int gid = (blockIdx.y * gridDim.x + blockIdx.x) * 256 + tid;   // 0..115199
        if (gid < GTOT / 4) {
            const float4* p0 = (const float4*)g_Gp;
            float4 v0 = p0[gid];
            float4 v1 = p0[GTOT / 4 + gid];
            float4 v2 = p0[2 * (GTOT / 4) + gid];
            float4 v3 = p0[3 * (GTOT / 4) + gid];
            float4 r;
            r.x = v0.x + v1.x + v2.x + v3.x;
            r.y = v0.y + v1.y + v2.y + v3.y;
            r.z = v0.z + v1.z + v2.z + v3.z;
            r.w = v0.w + v1.w + v2.w + v3.w;
            ((float4*)g_G)[gid] = r;
        }
    }

    float d[4][4][4] = {};

    for (int it = 0; it < NKSTEP; it++) {
        CP_WAIT2();
        __syncthreads();

        int kn = it + 3;
        if (kn < NKSTEP) {
            uint32_t ds = sbase + (kn & 3) * STAGE_B;
            cp_async16(ds + cp_off, a_src + kn * BK);
            cp_async16(ds + ATILE_B + cp_off, b_src + kn * BK);
        }
        CP_COMMIT();

        const uint32_t sb = sbase + (it & 3) * STAGE_B;
        uint32_t a[4][4];
        uint32_t b[4][2];
#pragma unroll
        for (int tm = 0; tm < 4; tm++) ldmx4(a[tm], sb + a_ld + tm * (16 * PITCH));
#pragma unroll
        for (int bt = 0; bt < 2; bt++) {
            uint32_t r[4];
            ldmx4(r, sb + ATILE_B + b_ld + bt * (16 * PITCH));
            b[bt * 2 + 0][0] = r[0]; b[bt * 2 + 0][1] = r[2];
            b[bt * 2 + 1][0] = r[1]; b[bt * 2 + 1][1] = r[3];
        }
#pragma unroll
        for (int tm = 0; tm < 4; tm++)
#pragma unroll
            for (int tn = 0; tn < 4; tn++)
                mma_fp16(d[tm][tn], a[tm], b[tn]);
    }

    const int mbase = bm0 + wm * 64 + (lane >> 2);
    const int nbase = bn0 + wn * 32 + (lane & 3) * 2;
#pragma unroll
    for (int tm = 0; tm < 4; tm++) {
#pragma unroll
        for (int tn = 0; tn < 4; tn++) {
            float* p = g_S + (size_t)(mbase + tm * 16) * NN + nbase + tn * 8;
            *(float2*)p            = make_float2(d[tm][tn][0], d[tm][tn][1]);
            *(float2*)(p + 8 * NN) = make_float2(d[tm][tn][2], d[tm][tn][3]);
        }
    }
}

// ---------------- Kernel 4: attention epilogue, one CTA per (i,c), 8 warps ----------------
// R15 skeleton; caption inv-norms computed from the Gram diagonal in smem.
__global__ void attn_kernel(const int* __restrict__ img_lens, const int* __restrict__ cap_lens,
                            const float* __restrict__ alpha_p, float* __restrict__ out) {
    __shared__ float Gs[NW][NW + 3];
    __shared__ float attn_s[8][NW];
    int c = blockIdx.x, i = blockIdx.y;
    int tid = threadIdx.x;             // 256 threads
    int lane = tid & 31, wid = tid >> 5;

    // load fully-reduced Gram once per CTA
    for (int idx = tid; idx < NW * NW; idx += 256)
        Gs[idx / NW][idx % NW] = g_G[(size_t)c * NW * NW + idx];
    __syncthreads();

    float a = 1.0f / (1.0f + expf(-alpha_p[0]));
    int ilen = img_lens[i], clen = cap_lens[c];
    int cl4 = (clen + 3) & ~3;         // rounded up for unroll-4
    if (cl4 > NW) cl4 = NW;            // clamp: avoid OOB past 50-wide arrays

    int w0 = lane;
    int w1 = lane + 32;
    bool has1 = (w1 < NW);
    // caption inv-norms from the Gram diagonal: ||cap_w||^2 = G[w][w]
    float capinv0 = 1.0f / (sqrtf(Gs[w0][w0]) + EPSF);
    float capinv1 = has1 ? (1.0f / (sqrtf(Gs[w1][w1]) + EPSF)) : 0.f;
    bool v0 = (w0 < clen);
    bool v1 = has1 && (w1 < clen);

    for (int r = wid; r < NR; r += 8) {
        size_t oidx = ((size_t)i * NB + c) * NR + r;
        if (r >= ilen) {
            if (lane == 0) out[oidx] = -1.0f;
            continue;
        }
        const float* Srow = g_S + ((size_t)(i * NR + r)) * NN + c * NW;
        float s0 = Srow[w0];
        float s1 = has1 ? Srow[w1] : 0.f;
        float iinv = g_img_inv[i * NR + r];
        float sim0 = s0 * iinv * capinv0;
        float sim1 = s1 * iinv * capinv1;

        // argmax over words (masked = -1.0, first-index tie break)
        float m0 = v0 ? sim0 : -1.0f;
        float m1 = v1 ? sim1 : -1.0f;
        float bv; int bi;
        if (m1 > m0) { bv = m1; bi = w1; } else { bv = m0; bi = w0; }
#pragma unroll
        for (int off = 16; off; off >>= 1) {
            float ov = __shfl_xor_sync(0xffffffffu, bv, off);
            int   oi = __shfl_xor_sync(0xffffffffu, bi, off);
            if (ov > bv || (ov == bv && oi < bi)) { bv = ov; bi = oi; }
        }

        // stable masked softmax at T=0.1. max logit = 10*bv (cosines >= -1, clen >= 1)
        float mx = bv * 10.0f;
        float e0 = v0 ? __expf(sim0 * 10.0f - mx) : 0.f;
        float e1 = v1 ? __expf(sim1 * 10.0f - mx) : 0.f;
        float es = e0 + e1;
#pragma unroll
        for (int off = 16; off; off >>= 1) es += __shfl_xor_sync(0xffffffffu, es, off);
        float inv_es = 1.0f / es;

        float attn0 = v0 ? (a * e0 * inv_es + ((w0 == bi) ? (1.0f - a) : 0.f)) : 0.f;
        float attn1 = v1 ? (a * e1 * inv_es + ((w1 == bi) ? (1.0f - a) : 0.f)) : 0.f;

        float num = attn0 * s0 + attn1 * s1;

        attn_s[wid][w0] = attn0;
        if (has1) attn_s[wid][w1] = attn1;
        __syncwarp();
        // quadratic form bounded at clen (attn[w2]=0 beyond; cl4 clamped to NW)
        float vv0 = 0.f, vv1 = 0.f;
#pragma unroll 4
        for (int w2 = 0; w2 < cl4; w2++) {
            float at = attn_s[wid][w2];
            vv0 += Gs[w0][w2] * at;
            if (has1) vv1 += Gs[w1][w2] * at;
        }
        float qf = attn0 * vv0 + attn1 * vv1;

#pragma unroll
        for (int off = 16; off; off >>= 1) {
            num += __shfl_xor_sync(0xffffffffu, num, off);
            qf  += __shfl_xor_sync(0xffffffffu, qf, off);
        }

        if (lane == 0) out[oidx] = num / (sqrtf(qf) + EPSF);
        __syncwarp();
    }
}

extern "C" void kernel_launch(void* const* d_in, const int* in_sizes, int n_in,
                              void* d_out, int out_size) {
    const float* imgs     = (const float*)d_in[0];
    const float* caps     = (const float*)d_in[1];
    const int*   img_lens = (const int*)d_in[2];
    const int*   cap_lens = (const int*)d_in[3];
    const float* alpha    = (const float*)d_in[4];
    float* out = (float*)d_out;

    norms_kernel<<<MM / 8, 256>>>(imgs);
    convert_kernel<<<768, 256>>>(imgs);
    gram_kernel<<<dim3(NB, KSPLIT), 256>>>(caps);
    gemm_kernel<<<dim3(NN / BN, MM / BM), 256>>>();
    attn_kernel<<<dim3(NB, NB), 256>>>(img_lens, cap_lens, alpha, out);
}

// round 17
// speedup vs baseline: 1.0130x; 1.0130x over previous
#include <cuda_runtime.h>
#include <cuda_fp16.h>
#include <math.h>
#include <stdint.h>

#define NB 64
#define NR 36
#define NW 50
#define ND 1024
#define MM (NB*NR)    // 2304
#define NN (NB*NW)    // 3200
#define EPSF 1e-8f
#define KSPLIT 4

// ---------------- scratch (device globals) ----------------
__device__ float g_S[MM * NN];                 // unnormalized dot products, 29.5 MB
__device__ float g_Gp[KSPLIT * NB * NW * NW];  // partial Gram matrices
__device__ float g_G[NB * NW * NW];            // reduced Gram matrices
__device__ float g_img_inv[MM];
__device__ float g_cap_inv[NN];
__device__ __half g_A2[MM * ND];               // 4.7 MB (fp16)
__device__ __half g_B2[NN * ND];               // 6.6 MB (fp16)

// ---------------- small PTX helpers (sm_80-era, compute_103-safe) ----------------
__device__ __forceinline__ uint32_t smem_u32(const void* p) {
    uint32_t a;
    asm("{ .reg .u64 t; cvta.to.shared.u64 t, %1; cvt.u32.u64 %0, t; }" : "=r"(a) : "l"(p));
    return a;
}
__device__ __forceinline__ void cp_async16(uint32_t dst, const void* src) {
    asm volatile("cp.async.cg.shared.global [%0], [%1], 16;" :: "r"(dst), "l"(src) : "memory");
}
#define CP_COMMIT() asm volatile("cp.async.commit_group;" ::: "memory")
#define CP_WAIT2()  asm volatile("cp.async.wait_group 2;" ::: "memory")

__device__ __forceinline__ void ldmx4(uint32_t* r, uint32_t addr) {
    asm volatile("ldmatrix.sync.aligned.m8n8.x4.shared.b16 {%0,%1,%2,%3}, [%4];"
                 : "=r"(r[0]), "=r"(r[1]), "=r"(r[2]), "=r"(r[3]) : "r"(addr));
}
__device__ __forceinline__ void mma_fp16(float* d, const uint32_t* a, const uint32_t* b) {
    asm volatile(
        "mma.sync.aligned.m16n8k16.row.col.f32.f16.f16.f32 "
        "{%0,%1,%2,%3}, {%4,%5,%6,%7}, {%8,%9}, {%0,%1,%2,%3};"
        : "+f"(d[0]), "+f"(d[1]), "+f"(d[2]), "+f"(d[3])
        : "r"(a[0]), "r"(a[1]), "r"(a[2]), "r"(a[3]), "r"(b[0]), "r"(b[1]));
}

// ---------------- Kernel 1: inverse (norm + eps) for every img/cap row ----------------
__global__ void norms_kernel(const float* __restrict__ imgs, const float* __restrict__ caps) {
    int warp = (blockIdx.x * blockDim.x + threadIdx.x) >> 5;
    int lane = threadIdx.x & 31;
    if (warp >= MM + NN) return;
    const float* p = (warp < MM) ? (imgs + (size_t)warp * ND)
                                 : (caps + (size_t)(warp - MM) * ND);
    float s = 0.f;
#pragma unroll
    for (int k = 0; k < ND / 128; k++) {
        float4 v = *(const float4*)(p + (size_t)(k * 32 + lane) * 4);
        s += v.x * v.x + v.y * v.y + v.z * v.z + v.w * v.w;
    }
#pragma unroll
    for (int off = 16; off; off >>= 1) s += __shfl_xor_sync(0xffffffffu, s, off);
    if (lane == 0) {
        float inv = 1.0f / (sqrtf(s) + EPSF);
        if (warp < MM) g_img_inv[warp] = inv;
        else           g_cap_inv[warp - MM] = inv;
    }
}

// ---------------- Kernel 1b: fp32 -> fp16 conversion (grid-stride) ----------------
__global__ void convert_kernel(const float* __restrict__ imgs, const float* __restrict__ caps) {
    const int totA = MM * ND / 4;
    const int tot  = (MM + NN) * ND / 4;
    for (int i = blockIdx.x * blockDim.x + threadIdx.x; i < tot; i += gridDim.x * blockDim.x) {
        float4 v;
        __half* dst;
        int idx4;
        if (i < totA) {
            v = ((const float4*)imgs)[i];
            dst = g_A2; idx4 = i;
        } else {
            v = ((const float4*)caps)[i - totA];
            dst = g_B2; idx4 = i - totA;
        }
        __half hx = __float2half_rn(v.x), hy = __float2half_rn(v.y),
               hz = __float2half_rn(v.z), hw = __float2half_rn(v.w);
        __half2 h01; h01.x = hx; h01.y = hy;
        __half2 h23; h23.x = hz; h23.y = hw;
        uint2 hp;
        hp.x = *(uint32_t*)&h01; hp.y = *(uint32_t*)&h23;
        *(uint2*)(dst + (size_t)idx4 * 4) = hp;
    }
}

// ---------------- Kernel 2: per-caption Gram matrices (k-split x4, fp32 exact) ----------------
#define GK 128
__global__ void gram_kernel(const float* __restrict__ caps) {
    __shared__ float tile[NW][GK + 4];
    int c = blockIdx.x;
    int ks = blockIdx.y;
    const float* cp = caps + (size_t)c * NW * ND;
    int tid = threadIdx.x;               // 256 threads
    int tx = tid % 16, ty = tid / 16;
    float acc[4][4] = {};
    int k0 = ks * (ND / KSPLIT);
    for (int kt = k0; kt < k0 + ND / KSPLIT; kt += GK) {
        __syncthreads();
        for (int idx = tid; idx < NW * GK / 4; idx += 256) {
            int f = idx * 4;
            int w = f / GK, k = f % GK;
            float4 v = *(const float4*)(cp + (size_t)w * ND + kt + k);
            tile[w][k] = v.x; tile[w][k + 1] = v.y; tile[w][k + 2] = v.z; tile[w][k + 3] = v.w;
        }
        __syncthreads();
#pragma unroll 4
        for (int k = 0; k < GK; k++) {
            float a[4], b[4];
#pragma unroll
            for (int u = 0; u < 4; u++) { int w = ty + 16 * u; a[u] = (w < NW) ? tile[w][k] : 0.f; }
#pragma unroll
            for (int v2 = 0; v2 < 4; v2++) { int w = tx + 16 * v2; b[v2] = (w < NW) ? tile[w][k] : 0.f; }
#pragma unroll
            for (int u = 0; u < 4; u++)
#pragma unroll
                for (int v2 = 0; v2 < 4; v2++) acc[u][v2] += a[u] * b[v2];
        }
    }
    float* Gp = g_Gp + ((size_t)ks * NB + c) * NW * NW;
#pragma unroll
    for (int u = 0; u < 4; u++)
#pragma unroll
        for (int v2 = 0; v2 < 4; v2++) {
            int w = ty + 16 * u, w2 = tx + 16 * v2;
            if (w < NW && w2 < NW) Gp[w * NW + w2] = acc[u][v2];
        }
}

// ---------------- Kernel 3: fp16 mma.sync GEMM 128x128, K=1024, 4-stage cp.async ----
// (R13-proven: 57.9us. Prologue folds the Gram partial reduction.)
#define BM 128
#define BN 128
#define BK 16
#define NKSTEP (ND / BK)           // 64
#define PITCH 48                   // 32B data + 16B pad per row (conflict-free ldmatrix)
#define ATILE_B (BM * PITCH)       // 6144
#define STAGE_B (2 * ATILE_B)      // 12288
#define NSTAGE 4
#define GTOT (NB * NW * NW)        // 160000 floats = 40000 float4

__global__ void __launch_bounds__(256, 2)
gemm_kernel() {
    __shared__ __align__(128) char smem[NSTAGE * STAGE_B];   // 48 KB
    const int tid = threadIdx.x;
    const int lane = tid & 31;
    const int wid = tid >> 5;
    const int wm = wid & 1;        // 2 warp-rows  -> 64 rows each
    const int wn = wid >> 1;       // 4 warp-cols  -> 32 cols each
    const int bm0 = blockIdx.y * BM;
    const int bn0 = blockIdx.x * BN;

    const uint32_t sbase = smem_u32(smem);

    const int crow = tid >> 1;           // 0..127
    const int cch  = tid & 1;            // 0..1
    const uint32_t cp_off = (uint32_t)crow * PITCH + (uint32_t)cch * 16;
    const __half* a_src = g_A2 + (size_t)(bm0 + crow) * ND + cch * 8;
    const __half* b_src = g_B2 + (size_t)(bn0 + crow) * ND + cch * 8;

    const uint32_t a_ld = (uint32_t)(wm * 64 + (lane & 15)) * PITCH + (uint32_t)(lane >> 4) * 16;
    const uint32_t b_ld = (uint32_t)(wn * 32 + (lane & 15)) * PITCH + (uint32_t)(lane >> 4) * 16;

#pragma unroll
    for (int s = 0; s < 3; s++) {
        uint32_t d = sbase + s * STAGE_B;
        cp_async16(d + cp_off, a_src + s * BK);
        cp_async16(d + ATILE_B + cp_off, b_src + s * BK);
        CP_COMMIT();
    }

    // ---- folded Gram reduction (overlaps the async prologue) ----
    {
        int gid = (blockIdx.y * gridDim.x + blockIdx.x) * 256 + tid;   // 0..115199
        if (gid < GTOT / 4) {
            const float4* p0 = (const float4*)g_Gp;
            float4 v0 = p0[gid];
            float4 v1 = p0[GTOT / 4 + gid];
            float4 v2 = p0[2 * (GTOT / 4) + gid];
            float4 v3 = p0[3 * (GTOT / 4) + gid];
            float4 r;
            r.x = v0.x + v1.x + v2.x + v3.x;
            r.y = v0.y + v1.y + v2.y + v3.y;
            r.z = v0.z + v1.z + v2.z + v3.z;
            r.w = v0.w + v1.w + v2.w + v3.w;
            ((float4*)g_G)[gid] = r;
        }
    }

    float d[4][4][4] = {};

    for (int it = 0; it < NKSTEP; it++) {
        CP_WAIT2();
        __syncthreads();

        int kn = it + 3;
        if (kn < NKSTEP) {
            uint32_t ds = sbase + (kn & 3) * STAGE_B;
            cp_async16(ds + cp_off, a_src + kn * BK);
            cp_async16(ds + ATILE_B + cp_off, b_src + kn * BK);
        }
        CP_COMMIT();

        const uint32_t sb = sbase + (it & 3) * STAGE_B;
        uint32_t a[4][4];
        uint32_t b[4][2];
#pragma unroll
        for (int tm = 0; tm < 4; tm++) ldmx4(a[tm], sb + a_ld + tm * (16 * PITCH));
#pragma unroll
        for (int bt = 0; bt < 2; bt++) {
            uint32_t r[4];
            ldmx4(r, sb + ATILE_B + b_ld + bt * (16 * PITCH));
            b[bt * 2 + 0][0] = r[0]; b[bt * 2 + 0][1] = r[2];
            b[bt * 2 + 1][0] = r[1]; b[bt * 2 + 1][1] = r[3];
        }
#pragma unroll
        for (int tm = 0; tm < 4; tm++)
#pragma unroll
            for (int tn = 0; tn < 4; tn++)
                mma_fp16(d[tm][tn], a[tm], b[tn]);
    }

    const int mbase = bm0 + wm * 64 + (lane >> 2);
    const int nbase = bn0 + wn * 32 + (lane & 3) * 2;
#pragma unroll
    for (int tm = 0; tm < 4; tm++) {
#pragma unroll
        for (int tn = 0; tn < 4; tn++) {
            float* p = g_S + (size_t)(mbase + tm * 16) * NN + nbase + tn * 8;
            *(float2*)p            = make_float2(d[tm][tn][0], d[tm][tn][1]);
            *(float2*)(p + 8 * NN) = make_float2(d[tm][tn][2], d[tm][tn][3]);
        }
    }
}

// ---------------- Kernel 4: attention epilogue, one CTA per (i,c), 8 warps ----------------
// R15 skeleton; argmax and exp-sum reduced in ONE fused shuffle pass.
// Direct __expf(10*sim) is safe: sim in [-1,1] -> e in [4.5e-5, 2.2e4], fp32-safe,
// and attn = a*e/es is scale-invariant.
__global__ void attn_kernel(const int* __restrict__ img_lens, const int* __restrict__ cap_lens,
                            const float* __restrict__ alpha_p, float* __restrict__ out) {
    __shared__ float Gs[NW][NW + 3];
    __shared__ float attn_s[8][NW];
    int c = blockIdx.x, i = blockIdx.y;
    int tid = threadIdx.x;             // 256 threads
    int lane = tid & 31, wid = tid >> 5;

    // load fully-reduced Gram once per CTA
    for (int idx = tid; idx < NW * NW; idx += 256)
        Gs[idx / NW][idx % NW] = g_G[(size_t)c * NW * NW + idx];
    __syncthreads();

    float a = 1.0f / (1.0f + expf(-alpha_p[0]));
    int ilen = img_lens[i], clen = cap_lens[c];
    int cl4 = (clen + 3) & ~3;         // rounded up for unroll-4
    if (cl4 > NW) cl4 = NW;            // clamp: avoid OOB past 50-wide arrays

    int w0 = lane;
    int w1 = lane + 32;
    bool has1 = (w1 < NW);
    float capinv0 = g_cap_inv[c * NW + w0];
    float capinv1 = has1 ? g_cap_inv[c * NW + w1] : 0.f;
    bool v0 = (w0 < clen);
    bool v1 = has1 && (w1 < clen);

    for (int r = wid; r < NR; r += 8) {
        size_t oidx = ((size_t)i * NB + c) * NR + r;
        if (r >= ilen) {
            if (lane == 0) out[oidx] = -1.0f;
            continue;
        }
        const float* Srow = g_S + ((size_t)(i * NR + r)) * NN + c * NW;
        float s0 = Srow[w0];
        float s1 = has1 ? Srow[w1] : 0.f;
        float iinv = g_img_inv[i * NR + r];
        float sim0 = s0 * iinv * capinv0;
        float sim1 = s1 * iinv * capinv1;

        // direct exp (bounded logits); lanes-local argmax
        float e0 = v0 ? __expf(sim0 * 10.0f) : 0.f;
        float e1 = v1 ? __expf(sim1 * 10.0f) : 0.f;
        float es = e0 + e1;

        float m0 = v0 ? sim0 : -1.0f;
        float m1 = v1 ? sim1 : -1.0f;
        float bv; int bi;
        if (m1 > m0) { bv = m1; bi = w1; } else { bv = m0; bi = w0; }

        // fused single reduction pass: argmax (bv,bi) + exp-sum (es)
#pragma unroll
        for (int off = 16; off; off >>= 1) {
            float ov = __shfl_xor_sync(0xffffffffu, bv, off);
            int   oi = __shfl_xor_sync(0xffffffffu, bi, off);
            es += __shfl_xor_sync(0xffffffffu, es, off);
            if (ov > bv || (ov == bv && oi < bi)) { bv = ov; bi = oi; }
        }
        float inv_es = 1.0f / es;

        float attn0 = v0 ? (a * e0 * inv_es + ((w0 == bi) ? (1.0f - a) : 0.f)) : 0.f;
        float attn1 = v1 ? (a * e1 * inv_es + ((w1 == bi) ? (1.0f - a) : 0.f)) : 0.f;

        float num = attn0 * s0 + attn1 * s1;

        attn_s[wid][w0] = attn0;
        if (has1) attn_s[wid][w1] = attn1;
        __syncwarp();
        // quadratic form bounded at clen (attn[w2]=0 beyond; cl4 clamped to NW)
        float vv0 = 0.f, vv1 = 0.f;
#pragma unroll 4
        for (int w2 = 0; w2 < cl4; w2++) {
            float at = attn_s[wid][w2];
            vv0 += Gs[w0][w2] * at;
            if (has1) vv1 += Gs[w1][w2] * at;
        }
        float qf = attn0 * vv0 + attn1 * vv1;

        // fused num + qf reduction
#pragma unroll
        for (int off = 16; off; off >>= 1) {
            num += __shfl_xor_sync(0xffffffffu, num, off);
            qf  += __shfl_xor_sync(0xffffffffu, qf, off);
        }

        if (lane == 0) out[oidx] = num / (sqrtf(qf) + EPSF);
        __syncwarp();
    }
}

extern "C" void kernel_launch(void* const* d_in, const int* in_sizes, int n_in,
                              void* d_out, int out_size) {
    const float* imgs     = (const float*)d_in[0];
    const float* caps     = (const float*)d_in[1];
    const int*   img_lens = (const int*)d_in[2];
    const int*   cap_lens = (const int*)d_in[3];
    const float* alpha    = (const float*)d_in[4];
    float* out = (float*)d_out;

    norms_kernel<<<(MM + NN) / 8, 256>>>(imgs, caps);
    convert_kernel<<<1184, 256>>>(imgs, caps);
    gram_kernel<<<dim3(NB, KSPLIT), 256>>>(caps);
    gemm_kernel<<<dim3(NN / BN, MM / BM), 256>>>();
    attn_kernel<<<dim3(NB, NB), 256>>>(img_lens, cap_lens, alpha, out);
}